// round 10
// baseline (speedup 1.0000x reference)
#include <cuda_runtime.h>
#include <cuda_bf16.h>

// Shapes: b=2, n=1024, d=128, DEPTH=4
// d_out (fp32): [0,134217728) grads (2,1024,4,128,128)
//               [134217728,134348800) next_memories (2,4,128,128)
//               [134348800] losses.mean()

#define SPB 4          // samples per block in phase 1 (512 blocks)
#define SEG 128        // timesteps per scan group (G = 1024/SEG = 8)
#define NG  8

__device__ __align__(16) float g_WT[4 * 128 * 128];            // W transposed per layer
__device__ __align__(16) float g_At[2 * 4 * 128 * 1024];       // [b*4+l][i][t]  layer inputs, t-contiguous
__device__ __align__(16) float g_D [2 * 4 * 1024 * 128];       // [b*4+l][t][j]  deltas * (-lr*2/d)
__device__ __align__(16) float g_C [8 * (NG - 1) * 128 * 128]; // chunk sums, g=0..NG-2
__device__ float g_lossPart[512];

// ---------------------------------------------------------------------------
// Kernel 0: smem-tiled transpose  WT[l][j][i] = W[l][i][j]
// ---------------------------------------------------------------------------
__global__ void k_transpose(const float* __restrict__ W)
{
    __shared__ float tile[32][33];
    const int l = blockIdx.z;
    const int bx = blockIdx.x * 32, by = blockIdx.y * 32;
    const int tx = threadIdx.x, ty = threadIdx.y;
#pragma unroll
    for (int r = 0; r < 4; r++)
        tile[ty + r * 8][tx] = W[(l << 14) + (by + ty + r * 8) * 128 + bx + tx];
    __syncthreads();
#pragma unroll
    for (int r = 0; r < 4; r++)
        g_WT[(l << 14) + (bx + ty + r * 8) * 128 + by + tx] = tile[tx][ty + r * 8];
}

// ---------------------------------------------------------------------------
// Phase 1: per-sample forward + backward MLP -> a_l (transposed), delta_l
// (scaled by -lr*2/d). SPB=4 samples/block, 512 blocks.
// A is stored [i][t]: thread tid owns row i=tid and writes its 4 consecutive
// timesteps as one float4 (STG.128 per thread).
// ---------------------------------------------------------------------------
__global__ __launch_bounds__(128) void k_phase1(
    const float* __restrict__ seq, const float* __restrict__ W,
    const float* __restrict__ Wkv, const float* __restrict__ wlr)
{
    __shared__ float Sqx[128][SPB];     // seq transposed  [i][s]
    __shared__ float Hx [128][SPB];     // current layer input
    __shared__ float Xs[3][128][SPB];   // pre-activations x0,x1,x2
    __shared__ float Dx [128][SPB];     // current delta
    __shared__ float scale_s[SPB];
    __shared__ float red[SPB * 4];

    const int tid  = threadIdx.x;
    const int lane = tid & 31, wid = tid >> 5;
    const int samp0 = blockIdx.x * SPB;
    const int b  = samp0 >> 10;
    const int t0 = samp0 & 1023;
    const int bl0 = b * 4;
    // g_At address for this thread's row, this block's timesteps
    const int AtIdx = (tid << 10) + t0;   // + bl*131072

    // load seq rows (coalesced), stash transposed
    float sv[SPB];
#pragma unroll
    for (int s = 0; s < SPB; s++) sv[s] = seq[(samp0 + s) * 128 + tid];
    *(float4*)&Sqx[tid][0] = make_float4(sv[0], sv[1], sv[2], sv[3]);

    // adaptive_lr[s] = dot(seq_row, w_lr)
    {
        float wl = wlr[tid];
#pragma unroll
        for (int s = 0; s < SPB; s++) {
            float p = sv[s] * wl;
            p += __shfl_xor_sync(0xffffffffu, p, 16);
            p += __shfl_xor_sync(0xffffffffu, p, 8);
            p += __shfl_xor_sync(0xffffffffu, p, 4);
            p += __shfl_xor_sync(0xffffffffu, p, 2);
            p += __shfl_xor_sync(0xffffffffu, p, 1);
            if (lane == 0) red[s * 4 + wid] = p;
        }
    }
    __syncthreads();
    if (tid < SPB) {
        float lr = red[tid * 4 + 0] + red[tid * 4 + 1] + red[tid * 4 + 2] + red[tid * 4 + 3];
        scale_s[tid] = -lr * (2.0f / 128.0f);
    }

    // kv = seq_row @ Wkv : keys -> Hx (+g_At layer0), values -> regs
    float accv[SPB];
    {
        float acck[SPB];
#pragma unroll
        for (int s = 0; s < SPB; s++) { acck[s] = 0.f; accv[s] = 0.f; }
#pragma unroll 4
        for (int i = 0; i < 128; i++) {
            float wk = Wkv[i * 256 + tid];
            float wv = Wkv[i * 256 + 128 + tid];
            float4 hv = *(const float4*)&Sqx[i][0];
            acck[0] += hv.x * wk; acck[1] += hv.y * wk;
            acck[2] += hv.z * wk; acck[3] += hv.w * wk;
            accv[0] += hv.x * wv; accv[1] += hv.y * wv;
            accv[2] += hv.z * wv; accv[3] += hv.w * wv;
        }
        float4 kk = make_float4(acck[0], acck[1], acck[2], acck[3]);
        *(float4*)&Hx[tid][0] = kk;
        *(float4*)&g_At[(bl0 + 0) * 131072 + AtIdx] = kk;
    }
    __syncthreads();

    // forward
    float pred[SPB];
    for (int l = 0; l < 4; l++) {
        float acc[SPB];
#pragma unroll
        for (int s = 0; s < SPB; s++) acc[s] = 0.f;
        const float* Wl = W + (l << 14);
#pragma unroll 8
        for (int i = 0; i < 128; i++) {
            float w = Wl[(i << 7) + tid];
            float4 hv = *(const float4*)&Hx[i][0];
            acc[0] += hv.x * w; acc[1] += hv.y * w;
            acc[2] += hv.z * w; acc[3] += hv.w * w;
        }
        __syncthreads();
        if (l < 3) {
            float h[SPB];
#pragma unroll
            for (int s = 0; s < SPB; s++) {
                float x  = acc[s];
                float sg = 1.0f / (1.0f + __expf(-x));
                h[s]     = x * sg;
            }
            float4 hh = make_float4(h[0], h[1], h[2], h[3]);
            *(float4*)&g_At[(bl0 + l + 1) * 131072 + AtIdx] = hh;
            *(float4*)&Xs[l][tid][0] = make_float4(acc[0], acc[1], acc[2], acc[3]);
            *(float4*)&Hx[tid][0]    = hh;
            __syncthreads();
        } else {
#pragma unroll
            for (int s = 0; s < SPB; s++) pred[s] = acc[s];
        }
    }

    // loss + delta3
    float diff[SPB];
#pragma unroll
    for (int s = 0; s < SPB; s++) diff[s] = pred[s] - accv[s];
#pragma unroll
    for (int s = 0; s < SPB; s++) {
        float p = diff[s] * diff[s];
        p += __shfl_xor_sync(0xffffffffu, p, 16);
        p += __shfl_xor_sync(0xffffffffu, p, 8);
        p += __shfl_xor_sync(0xffffffffu, p, 4);
        p += __shfl_xor_sync(0xffffffffu, p, 2);
        p += __shfl_xor_sync(0xffffffffu, p, 1);
        if (lane == 0) red[s * 4 + wid] = p;
    }
    __syncthreads();
    if (tid == 0) {
        float tot = 0.f;
        for (int k2 = 0; k2 < SPB * 4; k2++) tot += red[k2];
        g_lossPart[blockIdx.x] = tot * (1.0f / 128.0f);
    }
    {
        const int Db = ((bl0 + 3) * 1024 + t0) * 128;
        float dl[SPB];
#pragma unroll
        for (int s = 0; s < SPB; s++) {
            dl[s] = scale_s[s] * diff[s];
            g_D[Db + s * 128 + tid] = dl[s];
        }
        *(float4*)&Dx[tid][0] = make_float4(dl[0], dl[1], dl[2], dl[3]);
    }
    __syncthreads();

    // backward: e = W^T delta (coalesced via WT), delta_{l-1} = e * silu'(x_{l-1})
    for (int l = 3; l >= 1; l--) {
        float acc[SPB];
#pragma unroll
        for (int s = 0; s < SPB; s++) acc[s] = 0.f;
        const float* WTl = g_WT + (l << 14);
#pragma unroll 8
        for (int j = 0; j < 128; j++) {
            float w = WTl[(j << 7) + tid];
            float4 dv = *(const float4*)&Dx[j][0];
            acc[0] += dv.x * w; acc[1] += dv.y * w;
            acc[2] += dv.z * w; acc[3] += dv.w * w;
        }
        __syncthreads();
        const int Db = ((bl0 + l - 1) * 1024 + t0) * 128;
        float4 xv = *(const float4*)&Xs[l - 1][tid][0];
        float xs[SPB] = {xv.x, xv.y, xv.z, xv.w};
        float dl[SPB];
#pragma unroll
        for (int s = 0; s < SPB; s++) {
            float x    = xs[s];
            float sg   = 1.0f / (1.0f + __expf(-x));
            float dsil = sg * (1.0f + x * (1.0f - sg));
            dl[s]      = acc[s] * dsil;
            g_D[Db + s * 128 + tid] = dl[s];
        }
        *(float4*)&Dx[tid][0] = make_float4(dl[0], dl[1], dl[2], dl[3]);
        __syncthreads();
    }
}

// ---------------------------------------------------------------------------
// Chunk sums: C[bl][g][i][j] = sum_{t in group g} a[i][t]*d[t][j], g=0..NG-2.
// Register-batched loads: 2 uniform LDG.128 (a) + 8 LDG.128 (dv) per 8 t.
// ---------------------------------------------------------------------------
__global__ __launch_bounds__(128) void k_chunksum()
{
    const int tid  = threadIdx.x;
    const int bl   = blockIdx.x >> 5;
    const int tile = blockIdx.x & 31;
    const int g    = blockIdx.y;
    const int iLocal = tid >> 5, jq = tid & 31;
    const int i = tile * 4 + iLocal;

    const float*  Atp = g_At + bl * 131072 + (i << 10);          // + t
    const float4* Dp  = (const float4*)(g_D + bl * 131072) + jq; // + t*32
    const int tBase = g * SEG;

    float4 acc = make_float4(0.f, 0.f, 0.f, 0.f);
    for (int t = tBase; t < tBase + SEG; t += 8) {
        float4 av0 = __ldg((const float4*)(Atp + t));
        float4 av1 = __ldg((const float4*)(Atp + t + 4));
        float4 dv[8];
#pragma unroll
        for (int u = 0; u < 8; u++) dv[u] = __ldg(Dp + (t + u) * 32);
        float a[8] = {av0.x, av0.y, av0.z, av0.w, av1.x, av1.y, av1.z, av1.w};
#pragma unroll
        for (int u = 0; u < 8; u++) {
            acc.x += a[u] * dv[u].x; acc.y += a[u] * dv[u].y;
            acc.z += a[u] * dv[u].z; acc.w += a[u] * dv[u].w;
        }
    }
    ((float4*)g_C)[((bl * (NG - 1) + g) << 12) + (i << 5) + jq] = acc;
}

// ---------------------------------------------------------------------------
// Phase 2: grouped inclusive scan streamed to d_out. grid (256, NG) = 2048
// blocks. Batch of 8 t: issue all loads (MLP~10), then 8 FMA+STG.128.
// ---------------------------------------------------------------------------
__global__ __launch_bounds__(128) void k_phase2(const float* __restrict__ W,
                                                float* __restrict__ out)
{
    const int tid  = threadIdx.x;
    const int bl   = blockIdx.x >> 5;
    const int tile = blockIdx.x & 31;
    const int g    = blockIdx.y;
    const int b = bl >> 2, l = bl & 3;
    const int iLocal = tid >> 5, jq = tid & 31;
    const int i = tile * 4 + iLocal;

    // deterministic loss reduction (phase-1 partials complete: prior kernel)
    if (blockIdx.x == 0 && g == 0 && tid < 32) {
        float s2 = 0.f;
        for (int k2 = tid; k2 < 512; k2 += 32) s2 += g_lossPart[k2];
        s2 += __shfl_xor_sync(0xffffffffu, s2, 16);
        s2 += __shfl_xor_sync(0xffffffffu, s2, 8);
        s2 += __shfl_xor_sync(0xffffffffu, s2, 4);
        s2 += __shfl_xor_sync(0xffffffffu, s2, 2);
        s2 += __shfl_xor_sync(0xffffffffu, s2, 1);
        if (tid == 0) out[134348800] = s2 * (1.0f / 2048.0f);
    }

    const float*  Atp = g_At + bl * 131072 + (i << 10);
    const float4* Dp  = (const float4*)(g_D + bl * 131072) + jq;
    const int tBase = g * SEG;

    // seed with prefix of prior chunk sums
    float4 acc = make_float4(0.f, 0.f, 0.f, 0.f);
    for (int gp = 0; gp < g; gp++) {
        float4 cv = ((const float4*)g_C)[((bl * (NG - 1) + gp) << 12) + (i << 5) + jq];
        acc.x += cv.x; acc.y += cv.y; acc.z += cv.z; acc.w += cv.w;
    }

    // out offset for (b,t,l,i,j) = b*67108864 + t*65536 + l*16384 + i*128 + jq*4
    float* p = out + (size_t)b * 67108864u + (size_t)tBase * 65536u
                   + (l << 14) + (i << 7) + (jq << 2);

    for (int t = tBase; t < tBase + SEG; t += 8) {
        float4 av0 = __ldg((const float4*)(Atp + t));
        float4 av1 = __ldg((const float4*)(Atp + t + 4));
        float4 dv[8];
#pragma unroll
        for (int u = 0; u < 8; u++) dv[u] = __ldg(Dp + (t + u) * 32);
        float a[8] = {av0.x, av0.y, av0.z, av0.w, av1.x, av1.y, av1.z, av1.w};
#pragma unroll
        for (int u = 0; u < 8; u++) {
            acc.x += a[u] * dv[u].x; acc.y += a[u] * dv[u].y;
            acc.z += a[u] * dv[u].z; acc.w += a[u] * dv[u].w;
            *(float4*)p = acc;                           // STG.128 coalesced
            p += 65536;
        }
    }

    // next_memories = W + grads[:, -1]  (only the last group holds the total)
    if (g == NG - 1) {
        const float* Wl = W + (l << 14);
        float4 wv = *(const float4*)(Wl + (i << 7) + (jq << 2));
        float4 nm = make_float4(acc.x + wv.x, acc.y + wv.y, acc.z + wv.z, acc.w + wv.w);
        size_t nmIdx = 134217728u + ((size_t)(b * 4 + l) << 14) + (i << 7) + (jq << 2);
        *(float4*)(out + nmIdx) = nm;
    }
}

// ---------------------------------------------------------------------------
extern "C" void kernel_launch(void* const* d_in, const int* in_sizes, int n_in,
                              void* d_out, int out_size)
{
    (void)in_sizes; (void)n_in; (void)out_size;
    const float* seq = (const float*)d_in[0];
    const float* W   = (const float*)d_in[1];
    const float* Wkv = (const float*)d_in[2];
    const float* wlr = (const float*)d_in[3];
    // d_in[4] (w_mom), d_in[5] (w_decay) do not affect the outputs.
    float* out = (float*)d_out;

    k_transpose<<<dim3(4, 4, 4), dim3(32, 8)>>>(W);
    k_phase1<<<512, 128>>>(seq, W, Wkv, wlr);
    k_chunksum<<<dim3(256, NG - 1), 128>>>();
    k_phase2<<<dim3(256, NG), 128>>>(W, out);
}

// round 11
// speedup vs baseline: 1.0911x; 1.0911x over previous
#include <cuda_runtime.h>
#include <cuda_bf16.h>

// Shapes: b=2, n=1024, d=128, DEPTH=4
// d_out (fp32): [0,134217728) grads (2,1024,4,128,128)
//               [134217728,134348800) next_memories (2,4,128,128)
//               [134348800] losses.mean()

#define SPB 4          // samples per block in phase 1 (512 blocks)
#define TC  32         // timestep chunk staged in smem (phase 2 / chunksum)
#define SEG 128        // timesteps per scan group (G = 1024/SEG = 8)
#define NG  8

__device__ __align__(16) float g_WT[4 * 128 * 128];            // W transposed per layer
__device__ __align__(16) float g_A [2 * 4 * 1024 * 128];       // [b*4+l][t][i]  layer inputs a_l
__device__ __align__(16) float g_D [2 * 4 * 1024 * 128];       // [b*4+l][t][j]  deltas * (-lr*2/d)
__device__ __align__(16) float g_C [8 * (NG - 1) * 128 * 128]; // chunk sums, g=0..NG-2
__device__ float g_lossPart[512];

// ---------------------------------------------------------------------------
// Kernel 0: smem-tiled transpose  WT[l][j][i] = W[l][i][j]
// ---------------------------------------------------------------------------
__global__ void k_transpose(const float* __restrict__ W)
{
    __shared__ float tile[32][33];
    const int l = blockIdx.z;
    const int bx = blockIdx.x * 32, by = blockIdx.y * 32;
    const int tx = threadIdx.x, ty = threadIdx.y;
#pragma unroll
    for (int r = 0; r < 4; r++)
        tile[ty + r * 8][tx] = W[(l << 14) + (by + ty + r * 8) * 128 + bx + tx];
    __syncthreads();
#pragma unroll
    for (int r = 0; r < 4; r++)
        g_WT[(l << 14) + (bx + ty + r * 8) * 128 + by + tx] = tile[tx][ty + r * 8];
}

// ---------------------------------------------------------------------------
// Phase 1: per-sample forward + backward MLP -> a_l, delta_l (scaled by
// -lr*2/d). SPB=4 samples/block, 512 blocks. All global stores coalesced
// ([t][i] layout: consecutive tid -> consecutive address).
// ---------------------------------------------------------------------------
__global__ __launch_bounds__(128) void k_phase1(
    const float* __restrict__ seq, const float* __restrict__ W,
    const float* __restrict__ Wkv, const float* __restrict__ wlr)
{
    __shared__ float Sqx[128][SPB];     // seq transposed  [i][s]
    __shared__ float Hx [128][SPB];     // current layer input
    __shared__ float Xs[3][128][SPB];   // pre-activations x0,x1,x2
    __shared__ float Dx [128][SPB];     // current delta
    __shared__ float scale_s[SPB];
    __shared__ float red[SPB * 4];

    const int tid  = threadIdx.x;
    const int lane = tid & 31, wid = tid >> 5;
    const int samp0 = blockIdx.x * SPB;
    const int b  = samp0 >> 10;
    const int t0 = samp0 & 1023;
    const int bl0 = b * 4;

    // load seq rows (coalesced), stash transposed
    float sv[SPB];
#pragma unroll
    for (int s = 0; s < SPB; s++) sv[s] = seq[(samp0 + s) * 128 + tid];
    *(float4*)&Sqx[tid][0] = make_float4(sv[0], sv[1], sv[2], sv[3]);

    // adaptive_lr[s] = dot(seq_row, w_lr)
    {
        float wl = wlr[tid];
#pragma unroll
        for (int s = 0; s < SPB; s++) {
            float p = sv[s] * wl;
            p += __shfl_xor_sync(0xffffffffu, p, 16);
            p += __shfl_xor_sync(0xffffffffu, p, 8);
            p += __shfl_xor_sync(0xffffffffu, p, 4);
            p += __shfl_xor_sync(0xffffffffu, p, 2);
            p += __shfl_xor_sync(0xffffffffu, p, 1);
            if (lane == 0) red[s * 4 + wid] = p;
        }
    }
    __syncthreads();
    if (tid < SPB) {
        float lr = red[tid * 4 + 0] + red[tid * 4 + 1] + red[tid * 4 + 2] + red[tid * 4 + 3];
        scale_s[tid] = -lr * (2.0f / 128.0f);
    }

    // kv = seq_row @ Wkv : keys -> Hx (+g_A layer0), values -> regs
    float accv[SPB];
    {
        float acck[SPB];
#pragma unroll
        for (int s = 0; s < SPB; s++) { acck[s] = 0.f; accv[s] = 0.f; }
#pragma unroll 4
        for (int i = 0; i < 128; i++) {
            float wk = Wkv[i * 256 + tid];
            float wv = Wkv[i * 256 + 128 + tid];
            float4 hv = *(const float4*)&Sqx[i][0];
            acck[0] += hv.x * wk; acck[1] += hv.y * wk;
            acck[2] += hv.z * wk; acck[3] += hv.w * wk;
            accv[0] += hv.x * wv; accv[1] += hv.y * wv;
            accv[2] += hv.z * wv; accv[3] += hv.w * wv;
        }
        const int Ab = ((bl0 + 0) * 1024 + t0) * 128;
        *(float4*)&Hx[tid][0] = make_float4(acck[0], acck[1], acck[2], acck[3]);
#pragma unroll
        for (int s = 0; s < SPB; s++) g_A[Ab + s * 128 + tid] = acck[s];
    }
    __syncthreads();

    // forward
    float pred[SPB];
    for (int l = 0; l < 4; l++) {
        float acc[SPB];
#pragma unroll
        for (int s = 0; s < SPB; s++) acc[s] = 0.f;
        const float* Wl = W + (l << 14);
#pragma unroll 8
        for (int i = 0; i < 128; i++) {
            float w = Wl[(i << 7) + tid];
            float4 hv = *(const float4*)&Hx[i][0];
            acc[0] += hv.x * w; acc[1] += hv.y * w;
            acc[2] += hv.z * w; acc[3] += hv.w * w;
        }
        __syncthreads();
        if (l < 3) {
            const int Ab = ((bl0 + l + 1) * 1024 + t0) * 128;
            float h[SPB];
#pragma unroll
            for (int s = 0; s < SPB; s++) {
                float x  = acc[s];
                float sg = 1.0f / (1.0f + __expf(-x));
                h[s]     = x * sg;
                g_A[Ab + s * 128 + tid] = h[s];
            }
            *(float4*)&Xs[l][tid][0] = make_float4(acc[0], acc[1], acc[2], acc[3]);
            *(float4*)&Hx[tid][0]    = make_float4(h[0], h[1], h[2], h[3]);
            __syncthreads();
        } else {
#pragma unroll
            for (int s = 0; s < SPB; s++) pred[s] = acc[s];
        }
    }

    // loss + delta3
    float diff[SPB];
#pragma unroll
    for (int s = 0; s < SPB; s++) diff[s] = pred[s] - accv[s];
#pragma unroll
    for (int s = 0; s < SPB; s++) {
        float p = diff[s] * diff[s];
        p += __shfl_xor_sync(0xffffffffu, p, 16);
        p += __shfl_xor_sync(0xffffffffu, p, 8);
        p += __shfl_xor_sync(0xffffffffu, p, 4);
        p += __shfl_xor_sync(0xffffffffu, p, 2);
        p += __shfl_xor_sync(0xffffffffu, p, 1);
        if (lane == 0) red[s * 4 + wid] = p;
    }
    __syncthreads();
    if (tid == 0) {
        float tot = 0.f;
        for (int k2 = 0; k2 < SPB * 4; k2++) tot += red[k2];
        g_lossPart[blockIdx.x] = tot * (1.0f / 128.0f);
    }
    {
        const int Db = ((bl0 + 3) * 1024 + t0) * 128;
        float dl[SPB];
#pragma unroll
        for (int s = 0; s < SPB; s++) {
            dl[s] = scale_s[s] * diff[s];
            g_D[Db + s * 128 + tid] = dl[s];
        }
        *(float4*)&Dx[tid][0] = make_float4(dl[0], dl[1], dl[2], dl[3]);
    }
    __syncthreads();

    // backward: e = W^T delta (coalesced via WT), delta_{l-1} = e * silu'(x_{l-1})
    for (int l = 3; l >= 1; l--) {
        float acc[SPB];
#pragma unroll
        for (int s = 0; s < SPB; s++) acc[s] = 0.f;
        const float* WTl = g_WT + (l << 14);
#pragma unroll 8
        for (int j = 0; j < 128; j++) {
            float w = WTl[(j << 7) + tid];
            float4 dv = *(const float4*)&Dx[j][0];
            acc[0] += dv.x * w; acc[1] += dv.y * w;
            acc[2] += dv.z * w; acc[3] += dv.w * w;
        }
        __syncthreads();
        const int Db = ((bl0 + l - 1) * 1024 + t0) * 128;
        float4 xv = *(const float4*)&Xs[l - 1][tid][0];
        float xs[SPB] = {xv.x, xv.y, xv.z, xv.w};
        float dl[SPB];
#pragma unroll
        for (int s = 0; s < SPB; s++) {
            float x    = xs[s];
            float sg   = 1.0f / (1.0f + __expf(-x));
            float dsil = sg * (1.0f + x * (1.0f - sg));
            dl[s]      = acc[s] * dsil;
            g_D[Db + s * 128 + tid] = dl[s];
        }
        *(float4*)&Dx[tid][0] = make_float4(dl[0], dl[1], dl[2], dl[3]);
        __syncthreads();
    }
}

// ---------------------------------------------------------------------------
// Chunk sums: C[bl][g][i][j] = sum_{t in group g} a[t][i]*d[t][j], g=0..NG-2.
// Same smem-staged structure as phase 2 (minus the stores).
// ---------------------------------------------------------------------------
__global__ __launch_bounds__(128) void k_chunksum()
{
    __shared__ float4 dCh[TC * 32];
    __shared__ float  aCh[4][TC];

    const int tid  = threadIdx.x;
    const int bl   = blockIdx.x >> 5;
    const int tile = blockIdx.x & 31;
    const int g    = blockIdx.y;
    const int iLocal = tid >> 5, jq = tid & 31;
    const int i = tile * 4 + iLocal;

    const float*  Abl = g_A + bl * 131072;
    const float4* Dbl = (const float4*)(g_D + bl * 131072);
    const int tBase = g * SEG;

    float4 acc = make_float4(0.f, 0.f, 0.f, 0.f);
    for (int c = 0; c < SEG / TC; c++) {
        const float4* dsrc = Dbl + (tBase + c * TC) * 32;
#pragma unroll
        for (int k2 = 0; k2 < 8; k2++) dCh[tid + k2 * 128] = dsrc[tid + k2 * 128];
        {
            int tt = tid >> 2, il = tid & 3;
            aCh[il][tt] = Abl[(tBase + c * TC + tt) * 128 + tile * 4 + il];
        }
        __syncthreads();
#pragma unroll
        for (int tt = 0; tt < TC; tt++) {
            float  a  = aCh[iLocal][tt];
            float4 dv = dCh[tt * 32 + jq];
            acc.x += a * dv.x; acc.y += a * dv.y;
            acc.z += a * dv.z; acc.w += a * dv.w;
        }
        __syncthreads();
    }
    ((float4*)g_C)[((bl * (NG - 1) + g) << 12) + (i << 5) + jq] = acc;
}

// ---------------------------------------------------------------------------
// Phase 2: grouped inclusive scan streamed to d_out.
// grid (256, NG) = 2048 blocks (~13 co-resident blocks/SM).
// Smem-staged chunks: 8 back-to-back LDG.128 per thread decouple the load
// stream from the serial acc chain; a comes from broadcast LDS.
// ---------------------------------------------------------------------------
__global__ __launch_bounds__(128) void k_phase2(const float* __restrict__ W,
                                                float* __restrict__ out)
{
    __shared__ float4 dCh[TC * 32];
    __shared__ float  aCh[4][TC];

    const int tid  = threadIdx.x;
    const int bl   = blockIdx.x >> 5;
    const int tile = blockIdx.x & 31;
    const int g    = blockIdx.y;
    const int b = bl >> 2, l = bl & 3;
    const int iLocal = tid >> 5, jq = tid & 31;
    const int i = tile * 4 + iLocal;

    // deterministic loss reduction (phase-1 partials complete: prior kernel)
    if (blockIdx.x == 0 && g == 0 && tid < 32) {
        float s2 = 0.f;
        for (int k2 = tid; k2 < 512; k2 += 32) s2 += g_lossPart[k2];
        s2 += __shfl_xor_sync(0xffffffffu, s2, 16);
        s2 += __shfl_xor_sync(0xffffffffu, s2, 8);
        s2 += __shfl_xor_sync(0xffffffffu, s2, 4);
        s2 += __shfl_xor_sync(0xffffffffu, s2, 2);
        s2 += __shfl_xor_sync(0xffffffffu, s2, 1);
        if (tid == 0) out[134348800] = s2 * (1.0f / 2048.0f);
    }

    const float*  Abl = g_A + bl * 131072;
    const float4* Dbl = (const float4*)(g_D + bl * 131072);
    const int tBase = g * SEG;

    // seed with prefix of prior chunk sums
    float4 acc = make_float4(0.f, 0.f, 0.f, 0.f);
    for (int gp = 0; gp < g; gp++) {
        float4 cv = ((const float4*)g_C)[((bl * (NG - 1) + gp) << 12) + (i << 5) + jq];
        acc.x += cv.x; acc.y += cv.y; acc.z += cv.z; acc.w += cv.w;
    }

    // out offset for (b,t,l,i,j) = b*67108864 + t*65536 + l*16384 + i*128 + jq*4
    float* p = out + (size_t)b * 67108864u + (size_t)tBase * 65536u
                   + (l << 14) + (i << 7) + (jq << 2);

    for (int c = 0; c < SEG / TC; c++) {
        const float4* dsrc = Dbl + (tBase + c * TC) * 32;
#pragma unroll
        for (int k2 = 0; k2 < 8; k2++) dCh[tid + k2 * 128] = dsrc[tid + k2 * 128];
        {
            int tt = tid >> 2, il = tid & 3;
            aCh[il][tt] = Abl[(tBase + c * TC + tt) * 128 + tile * 4 + il];
        }
        __syncthreads();
#pragma unroll
        for (int tt = 0; tt < TC; tt++) {
            float  a  = aCh[iLocal][tt];
            float4 dv = dCh[tt * 32 + jq];
            acc.x += a * dv.x; acc.y += a * dv.y;
            acc.z += a * dv.z; acc.w += a * dv.w;
            *(float4*)p = acc;                           // STG.128 coalesced
            p += 65536;
        }
        __syncthreads();
    }

    // next_memories = W + grads[:, -1]  (only the last group holds the total)
    if (g == NG - 1) {
        const float* Wl = W + (l << 14);
        float4 wv = *(const float4*)(Wl + (i << 7) + (jq << 2));
        float4 nm = make_float4(acc.x + wv.x, acc.y + wv.y, acc.z + wv.z, acc.w + wv.w);
        size_t nmIdx = 134217728u + ((size_t)(b * 4 + l) << 14) + (i << 7) + (jq << 2);
        *(float4*)(out + nmIdx) = nm;
    }
}

// ---------------------------------------------------------------------------
extern "C" void kernel_launch(void* const* d_in, const int* in_sizes, int n_in,
                              void* d_out, int out_size)
{
    (void)in_sizes; (void)n_in; (void)out_size;
    const float* seq = (const float*)d_in[0];
    const float* W   = (const float*)d_in[1];
    const float* Wkv = (const float*)d_in[2];
    const float* wlr = (const float*)d_in[3];
    // d_in[4] (w_mom), d_in[5] (w_decay) do not affect the outputs.
    float* out = (float*)d_out;

    k_transpose<<<dim3(4, 4, 4), dim3(32, 8)>>>(W);
    k_phase1<<<512, 128>>>(seq, W, Wkv, wlr);
    k_chunksum<<<dim3(256, NG - 1), 128>>>();
    k_phase2<<<dim3(256, NG), 128>>>(W, out);
}